// round 2
// baseline (speedup 1.0000x reference)
#include <cuda_runtime.h>

// SoftDepthShader: softmax depth blend over K=50 rasterizer slots per pixel.
// out[p] = (sum_k w_k * z_k + delta) / (sum_k w_k + delta)
//   w_k   = sigmoid(-dists/SIGMA) * mask * exp((z_inv_k - z_inv_max)/GAMMA)
//   z_inv = (ZFAR - z)/(ZFAR - ZNEAR) * mask,  z_inv_max = max(max_k z_inv, EPS)
//   delta = max(exp((EPS - z_inv_max)/GAMMA), EPS)
//
// NOTE: pix_to_face is int64 in the reference, but the harness only carries
// float32/int32/bf16 — it arrives as int32. Only the sign matters.

#define KSLOTS 50
#define SIGMA_INV 1.0e4f    // 1/1e-4
#define GAMMA_INV 1.0e4f    // 1/1e-4
#define ZFAR 100.0f
#define INV_RANGE (1.0f / 99.0f)   // 1/(ZFAR-ZNEAR)
#define EPSV 1e-10f

__global__ __launch_bounds__(256) void soft_depth_kernel(
    const float* __restrict__ zbuf,
    const float* __restrict__ dists,
    const int*   __restrict__ p2f,
    float* __restrict__ out,
    int npix)
{
    const int warp_global = (blockIdx.x * blockDim.x + threadIdx.x) >> 5;
    const int lane = threadIdx.x & 31;
    if (warp_global >= npix) return;

    const long long base = (long long)warp_global * KSLOTS;

    // ---- coalesced loads: lane l covers slots l and l+32 ----
    const int k1 = lane + 32;
    const bool act1 = (k1 < KSLOTS);   // lanes 0..17

    float z0 = __ldg(zbuf + base + lane);
    float d0 = __ldg(dists + base + lane);
    bool  m0 = __ldg(p2f + base + lane) >= 0;

    float z1 = 0.0f, d1 = 0.0f;
    bool  m1 = false;
    if (act1) {
        z1 = __ldg(zbuf + base + k1);
        d1 = __ldg(dists + base + k1);
        m1 = __ldg(p2f + base + k1) >= 0;
    }

    // ---- z_inv per slot (masked slots -> 0, matching reference) ----
    float zi0 = m0 ? (ZFAR - z0) * INV_RANGE : 0.0f;
    float zi1 = m1 ? (ZFAR - z1) * INV_RANGE : 0.0f;

    // ---- warp max reduction ----
    float zmax = fmaxf(zi0, zi1);
    #pragma unroll
    for (int off = 16; off > 0; off >>= 1)
        zmax = fmaxf(zmax, __shfl_xor_sync(0xFFFFFFFFu, zmax, off));
    zmax = fmaxf(zmax, EPSV);

    // ---- weights and weighted-depth sums ----
    // prob = sigmoid(-d/SIGMA) = 1/(1+exp(d/SIGMA))
    float w0 = 0.0f, w1 = 0.0f;
    if (m0) {
        float p = __fdividef(1.0f, 1.0f + __expf(d0 * SIGMA_INV));
        w0 = p * __expf((zi0 - zmax) * GAMMA_INV);
    }
    if (m1) {
        float p = __fdividef(1.0f, 1.0f + __expf(d1 * SIGMA_INV));
        w1 = p * __expf((zi1 - zmax) * GAMMA_INV);
    }

    float sum_w  = w0 + w1;
    float sum_wz = w0 * z0 + w1 * z1;

    #pragma unroll
    for (int off = 16; off > 0; off >>= 1) {
        sum_w  += __shfl_xor_sync(0xFFFFFFFFu, sum_w,  off);
        sum_wz += __shfl_xor_sync(0xFFFFFFFFu, sum_wz, off);
    }

    if (lane == 0) {
        float delta = fmaxf(__expf((EPSV - zmax) * GAMMA_INV), EPSV);
        // BG_BLUE = 1.0 -> numerator gets + delta * 1.0
        out[warp_global] = (sum_wz + delta) * __fdividef(1.0f, sum_w + delta);
    }
}

extern "C" void kernel_launch(void* const* d_in, const int* in_sizes, int n_in,
                              void* d_out, int out_size)
{
    const float* zbuf  = (const float*)d_in[0];
    const float* dists = (const float*)d_in[1];
    const int*   p2f   = (const int*)d_in[2];
    float*       out   = (float*)d_out;

    const int npix = in_sizes[0] / KSLOTS;   // 8*256*256 = 524288

    const int threads = 256;                  // 8 warps -> 8 pixels per block
    const int warps_per_block = threads / 32;
    const int blocks = (npix + warps_per_block - 1) / warps_per_block;

    soft_depth_kernel<<<blocks, threads>>>(zbuf, dists, p2f, out, npix);
}

// round 3
// speedup vs baseline: 1.2282x; 1.2282x over previous
#include <cuda_runtime.h>

// SoftDepthShader: softmax depth blend over K=50 rasterizer slots per pixel.
// out[p] = (sum_k w_k * z_k + delta) / (sum_k w_k + delta)
//   w_k   = sigmoid(-dists/SIGMA) * mask * exp((z_inv_k - z_inv_max)/GAMMA)
//   z_inv = (ZFAR - z)/(ZFAR - ZNEAR) * mask,  z_inv_max = max(max_k z_inv, EPS)
//   delta = max(exp((EPS - z_inv_max)/GAMMA), EPS)
//
// pix_to_face arrives as int32 (harness dtype set). Only the sign matters.
//
// Layout: one warp per pixel. Row = 50 elems = 200 B = 25 x 8 B, so lane l<25
// loads one float2/int2 per array (slots 2l, 2l+1). Max-reduce via REDUX.MAX
// on raw bits (valid: zi >= 0), sums via 5-level shfl butterfly.

#define KSLOTS 50
#define ZFAR 100.0f
#define INV_RANGE (1.0f / 99.0f)
#define EPSV 1e-10f
// exp(x/SIGMA) = exp2(x * SIGMA_INV_L2E),  SIGMA = GAMMA = 1e-4
#define SIG_L2E 1.4426950408889634e4f
#define GAM_L2E 1.4426950408889634e4f

__device__ __forceinline__ float fast_exp2(float x) {
    float y;
    asm("ex2.approx.ftz.f32 %0, %1;" : "=f"(y) : "f"(x));
    return y;
}

__global__ __launch_bounds__(256) void soft_depth_kernel(
    const float2* __restrict__ zbuf2,
    const float2* __restrict__ dists2,
    const int2*   __restrict__ p2f2,
    float* __restrict__ out)
{
    const int warp_global = (blockIdx.x * blockDim.x + threadIdx.x) >> 5;
    const int lane = threadIdx.x & 31;

    float2 z2 = make_float2(0.f, 0.f);
    bool m0 = false, m1 = false;
    float zi0 = 0.f, zi1 = 0.f;
    float w0 = 0.f, w1 = 0.f;

    if (lane < 25) {
        const int idx = warp_global * 25 + lane;   // < 13.1M, fits int
        z2        = __ldg(zbuf2  + idx);
        float2 d2 = __ldg(dists2 + idx);
        int2   p2 = __ldg(p2f2   + idx);
        m0 = p2.x >= 0;
        m1 = p2.y >= 0;
        zi0 = m0 ? (ZFAR - z2.x) * INV_RANGE : 0.f;
        zi1 = m1 ? (ZFAR - z2.y) * INV_RANGE : 0.f;
        // stash sigmoid args for after the max reduction
        w0 = d2.x;   // temp: dists
        w1 = d2.y;
    }

    // ---- warp max of zi (zi >= 0 so int-compare == float-compare) ----
    int zi_bits = __float_as_int(fmaxf(zi0, zi1));
    zi_bits = __reduce_max_sync(0xFFFFFFFFu, zi_bits);
    const float zmax = fmaxf(__int_as_float(zi_bits), EPSV);

    // ---- weights ----
    if (m0) {
        float prob = __fdividef(1.0f, 1.0f + fast_exp2(w0 * SIG_L2E));
        w0 = prob * fast_exp2((zi0 - zmax) * GAM_L2E);
    } else {
        w0 = 0.f;
    }
    if (m1) {
        float prob = __fdividef(1.0f, 1.0f + fast_exp2(w1 * SIG_L2E));
        w1 = prob * fast_exp2((zi1 - zmax) * GAM_L2E);
    } else {
        w1 = 0.f;
    }

    float sum_w  = w0 + w1;
    float sum_wz = fmaf(w0, z2.x, w1 * z2.y);

    #pragma unroll
    for (int off = 16; off > 0; off >>= 1) {
        sum_w  += __shfl_xor_sync(0xFFFFFFFFu, sum_w,  off);
        sum_wz += __shfl_xor_sync(0xFFFFFFFFu, sum_wz, off);
    }

    if (lane == 0) {
        float delta = fmaxf(fast_exp2((EPSV - zmax) * GAM_L2E), EPSV);
        out[warp_global] = (sum_wz + delta) * __fdividef(1.0f, sum_w + delta);
    }
}

extern "C" void kernel_launch(void* const* d_in, const int* in_sizes, int n_in,
                              void* d_out, int out_size)
{
    const float2* zbuf2  = (const float2*)d_in[0];
    const float2* dists2 = (const float2*)d_in[1];
    const int2*   p2f2   = (const int2*)d_in[2];
    float*        out    = (float*)d_out;

    const int npix = in_sizes[0] / KSLOTS;    // 524288
    const int threads = 256;                  // 8 warps = 8 pixels / block
    const int blocks = npix / (threads / 32); // exact: 65536

    soft_depth_kernel<<<blocks, threads>>>(zbuf2, dists2, p2f2, out);
}